// round 7
// baseline (speedup 1.0000x reference)
#include <cuda_runtime.h>
#include <cuda_fp16.h>
#include <cstdint>
#include <math.h>

// logits = x @ W^T + b ; softmax ; top-2 ; renormalize.
// fp16 split GEMM (hh+hl+lh) via mma.sync m16n8k16:
//  - W pre-converted once to fp16 hi/lo (x64 scale)
//  - B: cp.async 2-stage ; A: LDG -> reg convert -> STS 2-stage
//  - 512 threads / 16 warps as kg(2) x 2M x 4N ; warp tile 64x32, split-K,
//    pair (w, w+8) reduced in the epilogue. One __syncthreads per chunk,
//    R6-proven ordering (wait_group -> barrier -> issue next -> compute).
// out[0:2T) = indices (as f32), out[2T:4T) = renormalized probs.

static constexpr int D_K  = 4096;
static constexpr int NE   = 128;
static constexpr int BM   = 128;
static constexpr int KC   = 32;                // k per chunk
static constexpr int NCH  = D_K / KC;          // 128
static constexpr int RS   = 40;                // halves per smem row (32 + 8 pad)
static constexpr int HT   = 128 * RS * 2;      // 10240 B per half-tile (hi or lo)
static constexpr int STG  = 2 * HT;            // hi+lo stage = 20480 B
static constexpr int A_OFF = 0;                // A stages: 2 * STG
static constexpr int B_OFF = 2 * STG;          // B stages: 2 * STG
static constexpr int SMEM_TOTAL = 4 * STG;     // 81920 B (>= 66048 epilogue)
static constexpr float WSCALE  = 64.0f;
static constexpr float IWSCALE = 1.0f / 64.0f;

__device__ __half2 gWhi[NE * D_K / 2];   // [e][k] row-major
__device__ __half2 gWlo[NE * D_K / 2];

__global__ void __launch_bounds__(256)
convW(const float* __restrict__ W)
{
    int i = blockIdx.x * 256 + threadIdx.x;          // over NE*D_K/2
    float2 w = reinterpret_cast<const float2*>(W)[i];
    float ax = w.x * WSCALE, ay = w.y * WSCALE;
    __half hx = __float2half_rn(ax), hy = __float2half_rn(ay);
    gWhi[i] = __halves2half2(hx, hy);
    gWlo[i] = __floats2half2_rn(ax - __half2float(hx), ay - __half2float(hy));
}

__device__ __forceinline__ uint32_t smem_u32(const void* p) {
    uint32_t a;
    asm("{ .reg .u64 t; cvta.to.shared.u64 t, %1; cvt.u32.u64 %0, t; }" : "=r"(a) : "l"(p));
    return a;
}

#define LDM4(r, addr)                                                            \
    asm volatile("ldmatrix.sync.aligned.m8n8.x4.shared.b16 {%0,%1,%2,%3}, [%4];" \
                 : "=r"((r)[0]), "=r"((r)[1]), "=r"((r)[2]), "=r"((r)[3])        \
                 : "r"(addr))

#define MMA16816(c, a, b0, b1)                                               \
    asm volatile("mma.sync.aligned.m16n8k16.row.col.f32.f16.f16.f32 "        \
                 "{%0,%1,%2,%3}, {%4,%5,%6,%7}, {%8,%9}, {%0,%1,%2,%3};"     \
                 : "+f"((c)[0]), "+f"((c)[1]), "+f"((c)[2]), "+f"((c)[3])    \
                 : "r"((a)[0]), "r"((a)[1]), "r"((a)[2]), "r"((a)[3]),       \
                   "r"(b0), "r"(b1))

#define CP16(dst, src) \
    asm volatile("cp.async.cg.shared.global [%0], [%1], 16;" :: "r"(dst), "l"(src))

__device__ __forceinline__ uint32_t pack_hi(float a, float b, float& la, float& lb) {
    __half ha = __float2half_rn(a);
    __half hb = __float2half_rn(b);
    la = a - __half2float(ha);
    lb = b - __half2float(hb);
    __half2 h = __halves2half2(ha, hb);
    return *reinterpret_cast<uint32_t*>(&h);
}
__device__ __forceinline__ uint32_t pack_lo(float a, float b) {
    __half2 h = __floats2half2_rn(a, b);
    return *reinterpret_cast<uint32_t*>(&h);
}

__global__ void __launch_bounds__(512, 1)
router_mma(const float* __restrict__ x, const float* __restrict__ bias,
           float* __restrict__ out, int T)
{
    extern __shared__ char smem[];
    const uint32_t sbase = smem_u32(smem);
    const int tid  = threadIdx.x;
    const int wid  = tid >> 5, lane = tid & 31;
    const int kg   = wid >> 3;          // k16-half of each chunk
    const int wm   = (wid >> 2) & 1;    // 2 M-groups (64 tokens)
    const int wn   = wid & 3;           // 4 N-groups (32 experts)
    const int t0   = blockIdx.x * BM;

    float acc[4][4][4];                 // [mt 0..3][n8 0..3][frag]
#pragma unroll
    for (int i = 0; i < 4; i++)
#pragma unroll
        for (int j = 0; j < 4; j++)
#pragma unroll
            for (int k = 0; k < 4; k++) acc[i][j][k] = 0.0f;

    // ---- A LDG slice: 1024 float4 per 128x32 f32 tile -> 2 per thread
    float4 araw[2];
    auto fetchA = [&](int cc) {
        const int k0 = cc * KC;
#pragma unroll
        for (int j = 0; j < 2; j++) {
            int i = tid + j * 512, row = i >> 3, c4 = i & 7;
            araw[j] = *reinterpret_cast<const float4*>(
                x + (size_t)(t0 + row) * D_K + k0 + c4 * 4);
        }
    };
    auto stsA = [&](int st) {
        char* base = smem + A_OFF + st * STG;
#pragma unroll
        for (int j = 0; j < 2; j++) {
            int i = tid + j * 512, row = i >> 3, c4 = i & 7;
            uint32_t off = (uint32_t)row * (RS * 2) + c4 * 8;
            float lx, ly, lz, lw;
            uint2 hi, lo;
            hi.x = pack_hi(araw[j].x, araw[j].y, lx, ly);
            hi.y = pack_hi(araw[j].z, araw[j].w, lz, lw);
            lo.x = pack_lo(lx, ly); lo.y = pack_lo(lz, lw);
            *reinterpret_cast<uint2*>(base + off)      = hi;
            *reinterpret_cast<uint2*>(base + HT + off) = lo;
        }
    };
    // cp.async B: 512 16B lines per half-tile, 1 per thread per half
    const char* whiB = reinterpret_cast<const char*>(gWhi);
    const char* wloB = reinterpret_cast<const char*>(gWlo);
    auto fillB = [&](int cc, int st) {
        const uint32_t sdst = sbase + B_OFF + st * STG;
        const int kByte = cc * KC * 2;
        int row = tid >> 2, c16 = tid & 3;
        uint32_t d = sdst + row * (RS * 2) + c16 * 16;
        size_t  go = (size_t)row * (D_K * 2) + kByte + c16 * 16;
        CP16(d,      whiB + go);
        CP16(d + HT, wloB + go);
        asm volatile("cp.async.commit_group;" ::: "memory");
    };

    // ---- prologue: chunk 0 -> stage 0 ; prefetch A chunk 1
    fetchA(0);
    stsA(0);
    fillB(0, 0);
    fetchA(1);

    const int ltile = lane >> 3, lr = lane & 7;
    const int lmoff = ((ltile & 1) * 8 + lr) * RS + (ltile >> 1) * 8;

    for (int c = 0; c < NCH; c++) {
        const int p = c & 1;

        asm volatile("cp.async.wait_group 0;" ::: "memory");
        __syncthreads();     // everyone's chunk-c copies + stage-p A visible;
                             // stage p^1 readers provably done

        if (c + 1 < NCH) {
            fillB(c + 1, p ^ 1);
            stsA(p ^ 1);                  // araw currently holds chunk c+1
            if (c + 2 < NCH) fetchA(c + 2);
        }

        const uint32_t aH = sbase + A_OFF + p * STG;
        const uint32_t bH = sbase + B_OFF + p * STG;
        // this warp computes only its kg'th k16 of the chunk
        const uint32_t kOff = (uint32_t)kg * 16;

        // B fragments for the warp's 32 experts (2 x 16-expert tiles, hi+lo)
        uint32_t Bh[2][4], Bl[2][4];
#pragma unroll
        for (int g = 0; g < 2; g++) {
            uint32_t off = (uint32_t)((wn * 32 + g * 16) * RS + kOff + lmoff) * 2;
            LDM4(Bh[g], bH + off);
            LDM4(Bl[g], bH + HT + off);
        }
#pragma unroll
        for (int mt = 0; mt < 4; mt++) {
            uint32_t Ah[4], Al[4];
            uint32_t off = (uint32_t)((wm * 64 + mt * 16) * RS + kOff + lmoff) * 2;
            LDM4(Ah, aH + off);
            LDM4(Al, aH + HT + off);
#pragma unroll
            for (int g = 0; g < 2; g++)
#pragma unroll
                for (int r = 0; r < 2; r++) {
                    float* a = acc[mt][g * 2 + r];
                    MMA16816(a, Ah, Bh[g][r], Bh[g][r + 2]);
                    MMA16816(a, Ah, Bl[g][r], Bl[g][r + 2]);
                    MMA16816(a, Al, Bh[g][r], Bh[g][r + 2]);
                }
        }
    }

    // ---- epilogue: reduce kg pairs, add bias, top-2 ----
    __syncthreads();
    float* lg = reinterpret_cast<float*>(smem);
    const int lr4 = lane >> 2, lc2 = (lane & 3) * 2;

    if (kg == 1) {   // partial sums -> smem
#pragma unroll
        for (int mt = 0; mt < 4; mt++)
#pragma unroll
            for (int nt = 0; nt < 4; nt++)
#pragma unroll
                for (int di = 0; di < 4; di++) {
                    int row = wm * 64 + mt * 16 + lr4 + (di >> 1) * 8;
                    int col = wn * 32 + nt * 8 + lc2 + (di & 1);
                    lg[row * 129 + col] = acc[mt][nt][di];
                }
    }
    __syncthreads();
    if (kg == 0) {   // combine + scale + bias
#pragma unroll
        for (int mt = 0; mt < 4; mt++)
#pragma unroll
            for (int nt = 0; nt < 4; nt++)
#pragma unroll
                for (int di = 0; di < 4; di++) {
                    int row = wm * 64 + mt * 16 + lr4 + (di >> 1) * 8;
                    int col = wn * 32 + nt * 8 + lc2 + (di & 1);
                    lg[row * 129 + col] =
                        (acc[mt][nt][di] + lg[row * 129 + col]) * IWSCALE
                        + __ldg(&bias[col]);
                }
    }
    __syncthreads();

    if (tid < BM) {
        const float* row = &lg[tid * 129];
        float v1 = -INFINITY, v2 = -INFINITY;
        int   i1 = 0, i2 = 0;
#pragma unroll 4
        for (int e = 0; e < NE; e++) {
            float v = row[e];
            if (v > v1)      { v2 = v1; i2 = i1; v1 = v; i1 = e; }
            else if (v > v2) { v2 = v;  i2 = e; }
        }
        float ssum = 0.0f;
#pragma unroll 4
        for (int e = 0; e < NE; e++) ssum += __expf(row[e] - v1);
        float p1 = 1.0f / ssum;
        float p2 = __expf(v2 - v1) / ssum;
        float den = p1 + p2 + 1e-8f;
        int t = t0 + tid;
        out[(size_t)t * 2 + 0] = (float)i1;
        out[(size_t)t * 2 + 1] = (float)i2;
        out[(size_t)2 * T + (size_t)t * 2 + 0] = p1 / den;
        out[(size_t)2 * T + (size_t)t * 2 + 1] = p2 / den;
    }
}

extern "C" void kernel_launch(void* const* d_in, const int* in_sizes, int n_in,
                              void* d_out, int out_size)
{
    const float* x = (const float*)d_in[0];
    const float* W = (const float*)d_in[1];
    const float* b = (const float*)d_in[2];
    float* out = (float*)d_out;

    int E = in_sizes[2];            // 128
    int D = in_sizes[1] / E;        // 4096
    int T = in_sizes[0] / D;        // 16384

    static int configured = -1;
    if (configured < 0) {
        cudaFuncSetAttribute(router_mma, cudaFuncAttributeMaxDynamicSharedMemorySize,
                             SMEM_TOTAL);
        configured = 1;
    }
    convW<<<(E * D / 2) / 256, 256>>>(W);
    router_mma<<<T / BM, 512, SMEM_TOTAL>>>(x, b, out, T);
}

// round 8
// speedup vs baseline: 1.1548x; 1.1548x over previous
#include <cuda_runtime.h>
#include <cuda_fp16.h>
#include <cstdint>
#include <math.h>

// logits = x @ W^T + b ; softmax ; top-2 ; renormalize.
// fp16 split GEMM (hh+hl+lh) via mma.sync m16n8k16.
// R8: R6 structure halved -> BM=64, 256 threads (8 warps, 2M x 4N, 32x32
// warp tiles), 2 CTAs per SM (independent barrier domains fill each other's
// stalls). W pre-converted to fp16 hi/lo; B cp.async 2-stage; A LDG->reg
// convert->STS 2-stage; one __syncthreads per chunk, R6-proven ordering.
// out[0:2T) = indices (as f32), out[2T:4T) = renormalized probs.

static constexpr int D_K  = 4096;
static constexpr int NE   = 128;
static constexpr int BM   = 64;                // tokens per CTA
static constexpr int KC   = 64;                // k per chunk
static constexpr int NCH  = D_K / KC;          // 64
static constexpr int RS   = 72;                // halves per smem row (64 + 8 pad)
static constexpr int HTA  = BM * RS * 2;       // 9216 B  (A half-tile)
static constexpr int HTB  = NE * RS * 2;       // 18432 B (B half-tile)
static constexpr int STGA = 2 * HTA;           // 18432 (hi+lo)
static constexpr int STGB = 2 * HTB;           // 36864
static constexpr int A_OFF = 0;                // 2 stages: 36864
static constexpr int B_OFF = 2 * STGA;         // 2 stages: 73728
static constexpr int SMEM_TOTAL = 2 * STGA + 2 * STGB;   // 110592 B
static constexpr float WSCALE  = 64.0f;
static constexpr float IWSCALE = 1.0f / 64.0f;

__device__ __half2 gWhi[NE * D_K / 2];   // [e][k] row-major
__device__ __half2 gWlo[NE * D_K / 2];

__global__ void __launch_bounds__(256)
convW(const float* __restrict__ W)
{
    int i = blockIdx.x * 256 + threadIdx.x;          // over NE*D_K/2
    float2 w = reinterpret_cast<const float2*>(W)[i];
    float ax = w.x * WSCALE, ay = w.y * WSCALE;
    __half hx = __float2half_rn(ax), hy = __float2half_rn(ay);
    gWhi[i] = __halves2half2(hx, hy);
    gWlo[i] = __floats2half2_rn(ax - __half2float(hx), ay - __half2float(hy));
}

__device__ __forceinline__ uint32_t smem_u32(const void* p) {
    uint32_t a;
    asm("{ .reg .u64 t; cvta.to.shared.u64 t, %1; cvt.u32.u64 %0, t; }" : "=r"(a) : "l"(p));
    return a;
}

#define LDM4(r, addr)                                                            \
    asm volatile("ldmatrix.sync.aligned.m8n8.x4.shared.b16 {%0,%1,%2,%3}, [%4];" \
                 : "=r"((r)[0]), "=r"((r)[1]), "=r"((r)[2]), "=r"((r)[3])        \
                 : "r"(addr))

#define MMA16816(c, a, b0, b1)                                               \
    asm volatile("mma.sync.aligned.m16n8k16.row.col.f32.f16.f16.f32 "        \
                 "{%0,%1,%2,%3}, {%4,%5,%6,%7}, {%8,%9}, {%0,%1,%2,%3};"     \
                 : "+f"((c)[0]), "+f"((c)[1]), "+f"((c)[2]), "+f"((c)[3])    \
                 : "r"((a)[0]), "r"((a)[1]), "r"((a)[2]), "r"((a)[3]),       \
                   "r"(b0), "r"(b1))

#define CP16(dst, src) \
    asm volatile("cp.async.cg.shared.global [%0], [%1], 16;" :: "r"(dst), "l"(src))

__device__ __forceinline__ uint32_t pack_hi(float a, float b, float& la, float& lb) {
    __half ha = __float2half_rn(a);
    __half hb = __float2half_rn(b);
    la = a - __half2float(ha);
    lb = b - __half2float(hb);
    __half2 h = __halves2half2(ha, hb);
    return *reinterpret_cast<uint32_t*>(&h);
}
__device__ __forceinline__ uint32_t pack_lo(float a, float b) {
    __half2 h = __floats2half2_rn(a, b);
    return *reinterpret_cast<uint32_t*>(&h);
}

__global__ void __launch_bounds__(256, 2)
router_mma(const float* __restrict__ x, const float* __restrict__ bias,
           float* __restrict__ out, int T)
{
    extern __shared__ char smem[];
    const uint32_t sbase = smem_u32(smem);
    const int tid  = threadIdx.x;
    const int wid  = tid >> 5, lane = tid & 31;
    const int wm   = wid >> 2;       // 2 M-groups (32 tokens)
    const int wn   = wid & 3;        // 4 N-groups (32 experts)
    const int t0   = blockIdx.x * BM;

    float acc[2][4][4];
#pragma unroll
    for (int i = 0; i < 2; i++)
#pragma unroll
        for (int j = 0; j < 4; j++)
#pragma unroll
            for (int k = 0; k < 4; k++) acc[i][j][k] = 0.0f;

    // ---- A LDG slice: 64x64 f32 tile = 1024 float4 -> 4 per thread
    float4 araw[4];
    auto fetchA = [&](int cc) {
        const int k0 = cc * KC;
#pragma unroll
        for (int j = 0; j < 4; j++) {
            int i = tid + j * 256, row = i >> 4, c4 = i & 15;
            araw[j] = *reinterpret_cast<const float4*>(
                x + (size_t)(t0 + row) * D_K + k0 + c4 * 4);
        }
    };
    auto stsA = [&](int st) {
        char* base = smem + A_OFF + st * STGA;
#pragma unroll
        for (int j = 0; j < 4; j++) {
            int i = tid + j * 256, row = i >> 4, c4 = i & 15;
            uint32_t off = (uint32_t)row * (RS * 2) + c4 * 8;
            float lx, ly, lz, lw;
            uint2 hi, lo;
            hi.x = pack_hi(araw[j].x, araw[j].y, lx, ly);
            hi.y = pack_hi(araw[j].z, araw[j].w, lz, lw);
            lo.x = pack_lo(lx, ly); lo.y = pack_lo(lz, lw);
            *reinterpret_cast<uint2*>(base + off)       = hi;
            *reinterpret_cast<uint2*>(base + HTA + off) = lo;
        }
    };
    // cp.async B: 128x64 fp16 half-tile = 1024 16B lines -> 4/thread per half
    const char* whiB = reinterpret_cast<const char*>(gWhi);
    const char* wloB = reinterpret_cast<const char*>(gWlo);
    auto fillB = [&](int cc, int st) {
        const uint32_t sdst = sbase + B_OFF + st * STGB;
        const int kByte = cc * KC * 2;
#pragma unroll
        for (int t = 0; t < 4; t++) {
            int i   = tid + t * 256;
            int row = i >> 3, c16 = i & 7;
            uint32_t d = sdst + row * (RS * 2) + c16 * 16;
            size_t  go = (size_t)row * (D_K * 2) + kByte + c16 * 16;
            CP16(d,       whiB + go);
            CP16(d + HTB, wloB + go);
        }
        asm volatile("cp.async.commit_group;" ::: "memory");
    };

    // ---- prologue: chunk 0 -> stage 0 ; prefetch A chunk 1
    fetchA(0);
    stsA(0);
    fillB(0, 0);
    fetchA(1);

    const int ltile = lane >> 3, lr = lane & 7;
    const int lmoff = ((ltile & 1) * 8 + lr) * RS + (ltile >> 1) * 8;

    for (int c = 0; c < NCH; c++) {
        const int p = c & 1;

        asm volatile("cp.async.wait_group 0;" ::: "memory");
        __syncthreads();     // everyone's chunk-c copies + stage-p A visible;
                             // stage p^1 readers provably done

        if (c + 1 < NCH) {
            fillB(c + 1, p ^ 1);
            stsA(p ^ 1);                  // araw currently holds chunk c+1
            if (c + 2 < NCH) fetchA(c + 2);
        }

        const uint32_t aH = sbase + A_OFF + p * STGA;
        const uint32_t bH = sbase + B_OFF + p * STGB;
#pragma unroll
        for (int kk = 0; kk < 4; kk++) {     // four k16 steps
            uint32_t Ah[2][4], Al[2][4];
#pragma unroll
            for (int mt = 0; mt < 2; mt++) {
                uint32_t off = (uint32_t)((wm * 32 + mt * 16) * RS + kk * 16 + lmoff) * 2;
                LDM4(Ah[mt], aH + off);
                LDM4(Al[mt], aH + HTA + off);
            }
#pragma unroll
            for (int g = 0; g < 2; g++) {    // two 16-expert blocks
                uint32_t Bh[4], Bl[4];
                uint32_t off = (uint32_t)((wn * 32 + g * 16) * RS + kk * 16 + lmoff) * 2;
                LDM4(Bh, bH + off);
                LDM4(Bl, bH + HTB + off);
#pragma unroll
                for (int mt = 0; mt < 2; mt++)
#pragma unroll
                    for (int r = 0; r < 2; r++) {
                        float* a = acc[mt][g * 2 + r];
                        MMA16816(a, Ah[mt], Bh[r], Bh[r + 2]);
                        MMA16816(a, Ah[mt], Bl[r], Bl[r + 2]);
                        MMA16816(a, Al[mt], Bh[r], Bh[r + 2]);
                    }
            }
        }
    }

    // ---- epilogue: logits (pitch 129), then per-token top-2 ----
    __syncthreads();
    float* lg = reinterpret_cast<float*>(smem);
    const int lr4 = lane >> 2, lc2 = (lane & 3) * 2;
#pragma unroll
    for (int mt = 0; mt < 2; mt++)
#pragma unroll
        for (int nt = 0; nt < 4; nt++)
#pragma unroll
            for (int di = 0; di < 4; di++) {
                int row = wm * 32 + mt * 16 + lr4 + (di >> 1) * 8;
                int col = wn * 32 + nt * 8 + lc2 + (di & 1);
                lg[row * 129 + col] = acc[mt][nt][di] * IWSCALE + __ldg(&bias[col]);
            }
    __syncthreads();

    if (tid < BM) {
        const float* row = &lg[tid * 129];
        float v1 = -INFINITY, v2 = -INFINITY;
        int   i1 = 0, i2 = 0;
#pragma unroll 4
        for (int e = 0; e < NE; e++) {
            float v = row[e];
            if (v > v1)      { v2 = v1; i2 = i1; v1 = v; i1 = e; }
            else if (v > v2) { v2 = v;  i2 = e; }
        }
        float ssum = 0.0f;
#pragma unroll 4
        for (int e = 0; e < NE; e++) ssum += __expf(row[e] - v1);
        float p1 = 1.0f / ssum;
        float p2 = __expf(v2 - v1) / ssum;
        float den = p1 + p2 + 1e-8f;
        int t = t0 + tid;
        out[(size_t)t * 2 + 0] = (float)i1;
        out[(size_t)t * 2 + 1] = (float)i2;
        out[(size_t)2 * T + (size_t)t * 2 + 0] = p1 / den;
        out[(size_t)2 * T + (size_t)t * 2 + 1] = p2 / den;
    }
}

extern "C" void kernel_launch(void* const* d_in, const int* in_sizes, int n_in,
                              void* d_out, int out_size)
{
    const float* x = (const float*)d_in[0];
    const float* W = (const float*)d_in[1];
    const float* b = (const float*)d_in[2];
    float* out = (float*)d_out;

    int E = in_sizes[2];            // 128
    int D = in_sizes[1] / E;        // 4096
    int T = in_sizes[0] / D;        // 16384

    static int configured = -1;
    if (configured < 0) {
        cudaFuncSetAttribute(router_mma, cudaFuncAttributeMaxDynamicSharedMemorySize,
                             SMEM_TOTAL);
        configured = 1;
    }
    convW<<<(E * D / 2) / 256, 256>>>(W);
    router_mma<<<T / BM, 256, SMEM_TOTAL>>>(x, b, out, T);
}

// round 9
// speedup vs baseline: 1.3299x; 1.1516x over previous
#include <cuda_runtime.h>
#include <cuda_fp16.h>
#include <cstdint>
#include <math.h>

// logits = x @ W^T + b ; softmax ; top-2 ; renormalize.
// fp16 split GEMM (hh+hl+lh) via mma.sync m16n8k16.
// R9: warp-specialized. 384 threads = 8 consumer warps (LDSM+MMA only,
// 2M x 4N, warp tile 64x32) + 4 producer warps (LDG A -> hi/lo convert ->
// STS ; cp.async B from pre-converted gW). Stage handoff via full/empty
// mbarriers, no __syncthreads in the main loop (decorrelates stalls).
// out[0:2T) = indices (as f32), out[2T:4T) = renormalized probs.

static constexpr int D_K  = 4096;
static constexpr int NE   = 128;
static constexpr int BM   = 128;
static constexpr int KC   = 64;
static constexpr int NCH  = D_K / KC;          // 64
static constexpr int RS   = 72;                // halves per smem row (64 + 8 pad)
static constexpr int HT   = 128 * RS * 2;      // 18432 B per half-tile
static constexpr int STG  = 2 * HT;            // hi+lo = 36864 B
static constexpr int A_OFF = 0;                // A stages: [0, 73728)
static constexpr int B_OFF = 2 * STG;          // B stages: [73728, 147456)
static constexpr int MB_OFF = 4 * STG;         // 4 mbarriers
static constexpr int SMEM_TOTAL = 4 * STG + 64;
static constexpr float WSCALE  = 64.0f;
static constexpr float IWSCALE = 1.0f / 64.0f;

__device__ __half2 gWhi[NE * D_K / 2];
__device__ __half2 gWlo[NE * D_K / 2];

__global__ void __launch_bounds__(256)
convW(const float* __restrict__ W)
{
    int i = blockIdx.x * 256 + threadIdx.x;
    float2 w = reinterpret_cast<const float2*>(W)[i];
    float ax = w.x * WSCALE, ay = w.y * WSCALE;
    __half hx = __float2half_rn(ax), hy = __float2half_rn(ay);
    gWhi[i] = __halves2half2(hx, hy);
    gWlo[i] = __floats2half2_rn(ax - __half2float(hx), ay - __half2float(hy));
}

__device__ __forceinline__ uint32_t smem_u32(const void* p) {
    uint32_t a;
    asm("{ .reg .u64 t; cvta.to.shared.u64 t, %1; cvt.u32.u64 %0, t; }" : "=r"(a) : "l"(p));
    return a;
}

#define LDM4(r, addr)                                                            \
    asm volatile("ldmatrix.sync.aligned.m8n8.x4.shared.b16 {%0,%1,%2,%3}, [%4];" \
                 : "=r"((r)[0]), "=r"((r)[1]), "=r"((r)[2]), "=r"((r)[3])        \
                 : "r"(addr))

#define MMA16816(c, a, b0, b1)                                               \
    asm volatile("mma.sync.aligned.m16n8k16.row.col.f32.f16.f16.f32 "        \
                 "{%0,%1,%2,%3}, {%4,%5,%6,%7}, {%8,%9}, {%0,%1,%2,%3};"     \
                 : "+f"((c)[0]), "+f"((c)[1]), "+f"((c)[2]), "+f"((c)[3])    \
                 : "r"((a)[0]), "r"((a)[1]), "r"((a)[2]), "r"((a)[3]),       \
                   "r"(b0), "r"(b1))

#define CP16(dst, src) \
    asm volatile("cp.async.cg.shared.global [%0], [%1], 16;" :: "r"(dst), "l"(src))

__device__ __forceinline__ void mbar_init(uint32_t a, uint32_t cnt) {
    asm volatile("mbarrier.init.shared.b64 [%0], %1;" :: "r"(a), "r"(cnt) : "memory");
}
__device__ __forceinline__ void mbar_arrive(uint32_t a) {
    asm volatile("mbarrier.arrive.release.cta.shared::cta.b64 _, [%0];" :: "r"(a) : "memory");
}
__device__ __forceinline__ void mbar_wait(uint32_t a, uint32_t parity) {
    asm volatile(
        "{\n\t.reg .pred P1;\n\t"
        "W%=:\n\t"
        "mbarrier.try_wait.parity.acquire.cta.shared::cta.b64 P1, [%0], %1, 0x989680;\n\t"
        "@P1 bra.uni DONE%=;\n\t"
        "bra.uni W%=;\n\t"
        "DONE%=:\n\t}"
        :: "r"(a), "r"(parity) : "memory");
}

__device__ __forceinline__ uint32_t pack_hi(float a, float b, float& la, float& lb) {
    __half ha = __float2half_rn(a);
    __half hb = __float2half_rn(b);
    la = a - __half2float(ha);
    lb = b - __half2float(hb);
    __half2 h = __halves2half2(ha, hb);
    return *reinterpret_cast<uint32_t*>(&h);
}
__device__ __forceinline__ uint32_t pack_lo(float a, float b) {
    __half2 h = __floats2half2_rn(a, b);
    return *reinterpret_cast<uint32_t*>(&h);
}

__global__ void __launch_bounds__(384, 1)
router_mma(const float* __restrict__ x, const float* __restrict__ bias,
           float* __restrict__ out, int T)
{
    extern __shared__ char smem[];
    const uint32_t sbase = smem_u32(smem);
    const int tid  = threadIdx.x;
    const int wid  = tid >> 5, lane = tid & 31;
    const int t0   = blockIdx.x * BM;

    // mbarriers: full[0], full[1], empty[0], empty[1]
    const uint32_t mFull0 = sbase + MB_OFF, mFull1 = mFull0 + 8;
    const uint32_t mEmp0  = mFull0 + 16,    mEmp1  = mFull0 + 24;
    if (tid == 0) {
        mbar_init(mFull0, 128); mbar_init(mFull1, 128);   // producers
        mbar_init(mEmp0, 256);  mbar_init(mEmp1, 256);    // consumers
    }
    __syncthreads();

    if (wid >= 8) {
        // ================= PRODUCER (4 warps, 128 threads) =================
        const int ptid = tid - 256;
        const char* whiB = reinterpret_cast<const char*>(gWhi);
        const char* wloB = reinterpret_cast<const char*>(gWlo);

        float4 araw[16];
        auto fetchA = [&](int cc) {
            const int k0 = cc * KC;
#pragma unroll
            for (int j = 0; j < 16; j++) {
                int i = ptid + j * 128, row = i >> 4, c4 = i & 15;
                araw[j] = *reinterpret_cast<const float4*>(
                    x + (size_t)(t0 + row) * D_K + k0 + c4 * 4);
            }
        };
        auto stsA = [&](int st) {
            char* base = smem + A_OFF + st * STG;
#pragma unroll
            for (int j = 0; j < 16; j++) {
                int i = ptid + j * 128, row = i >> 4, c4 = i & 15;
                uint32_t off = (uint32_t)row * (RS * 2) + c4 * 8;
                float lx, ly, lz, lw;
                uint2 hi, lo;
                hi.x = pack_hi(araw[j].x, araw[j].y, lx, ly);
                hi.y = pack_hi(araw[j].z, araw[j].w, lz, lw);
                lo.x = pack_lo(lx, ly); lo.y = pack_lo(lz, lw);
                *reinterpret_cast<uint2*>(base + off)      = hi;
                *reinterpret_cast<uint2*>(base + HT + off) = lo;
            }
        };
        auto fillB = [&](int cc, int st) {
            const uint32_t sdst = sbase + B_OFF + st * STG;
            const int kByte = cc * KC * 2;
#pragma unroll
            for (int t = 0; t < 8; t++) {
                int i   = ptid + t * 128;
                int row = i >> 3, c16 = i & 7;
                uint32_t d = sdst + row * (RS * 2) + c16 * 16;
                size_t  go = (size_t)row * (D_K * 2) + kByte + c16 * 16;
                CP16(d,      whiB + go);
                CP16(d + HT, wloB + go);
            }
            asm volatile("cp.async.commit_group;" ::: "memory");
        };

        int pe[2] = {0, 0};
        fetchA(0);
        for (int c = 0; c < NCH; c++) {
            const int s = c & 1;
            const uint32_t mE = s ? mEmp1 : mEmp0;
            const uint32_t mF = s ? mFull1 : mFull0;
            if (c >= 2) { mbar_wait(mE, pe[s]); pe[s] ^= 1; }
            stsA(s);                    // araw holds chunk c
            fillB(c, s);
            if (c + 1 < NCH) fetchA(c + 1);
            asm volatile("cp.async.wait_group 0;" ::: "memory");
            mbar_arrive(mF);
        }
        return;   // producers done
    }

    // ================= CONSUMER (8 warps, 256 threads) =================
    const int wm = wid >> 2;     // 2 M-groups (64 tokens)
    const int wn = wid & 3;      // 4 N-groups (32 experts)

    float acc[4][4][4];          // [mt 0..3][n8 0..3][frag]
#pragma unroll
    for (int i = 0; i < 4; i++)
#pragma unroll
        for (int j = 0; j < 4; j++)
#pragma unroll
            for (int k = 0; k < 4; k++) acc[i][j][k] = 0.0f;

    const int ltile = lane >> 3, lr = lane & 7;
    const int lmoff = ((ltile & 1) * 8 + lr) * RS + (ltile >> 1) * 8;

    int cf[2] = {0, 0};
    for (int c = 0; c < NCH; c++) {
        const int s = c & 1;
        const uint32_t mF = s ? mFull1 : mFull0;
        const uint32_t mE = s ? mEmp1 : mEmp0;
        mbar_wait(mF, cf[s]); cf[s] ^= 1;

        const uint32_t aH = sbase + A_OFF + s * STG;
        const uint32_t bH = sbase + B_OFF + s * STG;
#pragma unroll
        for (int kk = 0; kk < 4; kk++) {
            uint32_t Bh[2][4], Bl[2][4];
#pragma unroll
            for (int g = 0; g < 2; g++) {
                uint32_t off = (uint32_t)((wn * 32 + g * 16) * RS + kk * 16 + lmoff) * 2;
                LDM4(Bh[g], bH + off);
                LDM4(Bl[g], bH + HT + off);
            }
#pragma unroll
            for (int mt = 0; mt < 4; mt++) {
                uint32_t Ah[4], Al[4];
                uint32_t off = (uint32_t)((wm * 64 + mt * 16) * RS + kk * 16 + lmoff) * 2;
                LDM4(Ah, aH + off);
                LDM4(Al, aH + HT + off);
#pragma unroll
                for (int g = 0; g < 2; g++)
#pragma unroll
                    for (int r = 0; r < 2; r++) {
                        float* a = acc[mt][g * 2 + r];
                        MMA16816(a, Ah, Bh[g][r], Bh[g][r + 2]);
                        MMA16816(a, Ah, Bl[g][r], Bl[g][r + 2]);
                        MMA16816(a, Al, Bh[g][r], Bh[g][r + 2]);
                    }
            }
        }
        mbar_arrive(mE);
    }

    // ---- epilogue (consumers only): all 8 warps done before logits STS ----
    asm volatile("bar.sync 1, 256;" ::: "memory");

    float* lg = reinterpret_cast<float*>(smem);   // pitch 129, 66048 B
    const int lr4 = lane >> 2, lc2 = (lane & 3) * 2;
#pragma unroll
    for (int mt = 0; mt < 4; mt++)
#pragma unroll
        for (int nt = 0; nt < 4; nt++)
#pragma unroll
            for (int di = 0; di < 4; di++) {
                int row = wm * 64 + mt * 16 + lr4 + (di >> 1) * 8;
                int col = wn * 32 + nt * 8 + lc2 + (di & 1);
                lg[row * 129 + col] = acc[mt][nt][di] * IWSCALE + __ldg(&bias[col]);
            }
    asm volatile("bar.sync 1, 256;" ::: "memory");

    if (tid < BM) {
        const float* row = &lg[tid * 129];
        float v1 = -INFINITY, v2 = -INFINITY;
        int   i1 = 0, i2 = 0;
#pragma unroll 4
        for (int e = 0; e < NE; e++) {
            float v = row[e];
            if (v > v1)      { v2 = v1; i2 = i1; v1 = v; i1 = e; }
            else if (v > v2) { v2 = v;  i2 = e; }
        }
        float ssum = 0.0f;
#pragma unroll 4
        for (int e = 0; e < NE; e++) ssum += __expf(row[e] - v1);
        float p1 = 1.0f / ssum;
        float p2 = __expf(v2 - v1) / ssum;
        float den = p1 + p2 + 1e-8f;
        int t = t0 + tid;
        out[(size_t)t * 2 + 0] = (float)i1;
        out[(size_t)t * 2 + 1] = (float)i2;
        out[(size_t)2 * T + (size_t)t * 2 + 0] = p1 / den;
        out[(size_t)2 * T + (size_t)t * 2 + 1] = p2 / den;
    }
}

extern "C" void kernel_launch(void* const* d_in, const int* in_sizes, int n_in,
                              void* d_out, int out_size)
{
    const float* x = (const float*)d_in[0];
    const float* W = (const float*)d_in[1];
    const float* b = (const float*)d_in[2];
    float* out = (float*)d_out;

    int E = in_sizes[2];            // 128
    int D = in_sizes[1] / E;        // 4096
    int T = in_sizes[0] / D;        // 16384

    static int configured = -1;
    if (configured < 0) {
        cudaFuncSetAttribute(router_mma, cudaFuncAttributeMaxDynamicSharedMemorySize,
                             SMEM_TOTAL);
        configured = 1;
    }
    convW<<<(E * D / 2) / 256, 256>>>(W);
    router_mma<<<T / BM, 384, SMEM_TOTAL>>>(x, b, out, T);
}